// round 5
// baseline (speedup 1.0000x reference)
#include <cuda_runtime.h>
#include <math.h>

#define NG 256
#define NB 8
#define NPTS (NB*NG*NG)
#define TSTEPS 8
#define INNERS 10
#define K2P 132            // padded half-spectrum columns (0..128 used)

#define INVDX     40.743665431525205f        // 256/(2*pi)
#define INVDX2    (INVDX*INVDX)
#define VISCF     1e-3f
#define ONE65536  1.52587890625e-5f          // 1/65536

// ---------------- scratch (no allocation allowed) ----------------
__device__ float  g_u [NPTS];
__device__ float  g_v [NPTS];
__device__ float  g_d0[NPTS];
__device__ float  g_d1[NPTS];
__device__ float  g_u1[NPTS];
__device__ float  g_v1[NPTS];
__device__ float  g_q [NPTS];
__device__ float2 g_G [NB*NG*K2P];   // half-spectrum scratch, layout [b][i][k2]
__device__ float  g_lam1[NG];        // FD laplacian 1D eigenvalues

// ---------------- tables ----------------
__global__ void k_tables(){
    int t = threadIdx.x;   // 256 threads
    float sn = sinpif(t*(1.0f/256.0f));
    g_lam1[t] = -4.0f*sn*sn*INVDX2;  // = (2cos(2pi k/N)-2)/DX^2, cancellation-free
}

// ---------------- init: de-interleave y0 ----------------
__global__ void k_init(const float* __restrict__ y0){
    int idx = blockIdx.x*256 + threadIdx.x;
    int b   = idx >> 16;
    int ij  = idx & 0xFFFF;
    const float* p = y0 + (size_t)b*(NG*NG*3) + (size_t)ij*3;
    g_u [idx] = p[0];
    g_v [idx] = p[1];
    g_d0[idx] = p[2];
}

// ---------------- complex helpers ----------------
__device__ __forceinline__ float2 cadd(float2 a, float2 b){ return make_float2(a.x+b.x, a.y+b.y); }
__device__ __forceinline__ float2 csub(float2 a, float2 b){ return make_float2(a.x-b.x, a.y-b.y); }
__device__ __forceinline__ float2 cmul(float2 a, float2 b){
    return make_float2(fmaf(a.x,b.x,-a.y*b.y), fmaf(a.x,b.y,a.y*b.x));
}

// ---------------- per-thread 8-point DFT (sign S: -1 fwd, +1 inv), natural-order out ----------------
template<int S>
__device__ __forceinline__ void dft8(const float2 x[8], float2 A[8]){
    const float R = 0.70710678118654752f;
    float2 b0=cadd(x[0],x[4]), b1=cadd(x[1],x[5]), b2=cadd(x[2],x[6]), b3=cadd(x[3],x[7]);
    float2 t4=csub(x[0],x[4]), t5=csub(x[1],x[5]), t6=csub(x[2],x[6]), t7=csub(x[3],x[7]);
    float2 b4=t4;
    float2 b5=cmul(t5, make_float2(R, S*R));
    float2 b6=make_float2(-S*t6.y, S*t6.x);            // t6 * (0,S)
    float2 b7=cmul(t7, make_float2(-R, S*R));
    float2 c0=cadd(b0,b2), c1=cadd(b1,b3), c2=csub(b0,b2);
    float2 u3=csub(b1,b3); float2 c3=make_float2(-S*u3.y, S*u3.x);
    float2 c4=cadd(b4,b6), c5=cadd(b5,b7), c6=csub(b4,b6);
    float2 u7=csub(b5,b7); float2 c7=make_float2(-S*u7.y, S*u7.x);
    A[0]=cadd(c0,c1); A[4]=csub(c0,c1);
    A[2]=cadd(c2,c3); A[6]=csub(c2,c3);
    A[1]=cadd(c4,c5); A[5]=csub(c4,c5);
    A[3]=cadd(c6,c7); A[7]=csub(c6,c7);
}

// ---------------- cross-lane radix-2 butterfly stage ----------------
__device__ __forceinline__ void butterfly(float2 v[8], int mask, float2 w, bool up){
    #pragma unroll
    for (int j = 0; j < 8; j++){
        float px = __shfl_xor_sync(0xffffffffu, v[j].x, mask);
        float py = __shfl_xor_sync(0xffffffffu, v[j].y, mask);
        float dx = px - v[j].x, dy = py - v[j].y;
        float sx = v[j].x + px, sy = v[j].y + py;
        float rx = fmaf(dx, w.x, -dy*w.y);
        float ry = fmaf(dx, w.y,  dy*w.x);
        v[j].x = up ? rx : sx;
        v[j].y = up ? ry : sy;
    }
}

// ---------------- warp-level 256-pt FFT ----------------
// Input:  v[m] = x[lane + 32*m]  (natural order)
// Output: v[j] = X[j + 8*br5(lane)]   (br5 = 5-bit bit reversal)
// No normalization. S=-1 forward, S=+1 inverse.
template<int S>
__device__ __forceinline__ void warp_fft256(float2 v[8], int lane){
    float2 A[8];
    dft8<S>(v, A);
    float s, c;
    sincospif(lane*(1.0f/128.0f), &s, &c);
    float2 wt = make_float2(c, S*s);                // W256^(S*lane)
    v[0] = A[0];
    float2 w = wt;
    v[1] = cmul(A[1], w);
    #pragma unroll
    for (int j = 2; j < 8; j++){ w = cmul(w, wt); v[j] = cmul(A[j], w); }
    float2 ws;
    sincospif((lane&15)*(1.0f/16.0f), &s, &c); ws = make_float2(c, S*s);
    butterfly(v, 16, ws, (lane&16)!=0);
    sincospif((lane&7 )*(1.0f/8.0f ), &s, &c); ws = make_float2(c, S*s);
    butterfly(v, 8,  ws, (lane&8 )!=0);
    sincospif((lane&3 )*(1.0f/4.0f ), &s, &c); ws = make_float2(c, S*s);
    butterfly(v, 4,  ws, (lane&4 )!=0);
    ws = (lane&1) ? make_float2(0.f, (float)S) : make_float2(1.f, 0.f);
    butterfly(v, 2,  ws, (lane&2 )!=0);
    butterfly(v, 1,  make_float2(1.f, 0.f), (lane&1)!=0);
}

// ---------------- van-Leer limited face flux ----------------
__device__ __forceinline__ float face_flux(float cm1, float c0, float c1, float c2,
                                           float uf, float dtdx){
    float dc     = c1 - c0;
    float f_low  = (uf >= 0.0f) ? uf*c0 : uf*c1;
    float f_high = uf*0.5f*(c0+c1) - 0.5f*uf*uf*dtdx*dc;
    float dc_up  = (uf >= 0.0f) ? (c0 - cm1) : (c2 - c1);
    float dc_safe = (fabsf(dc) > 1e-12f) ? dc : 1e-12f;
    float phi = (dc_up * dc_safe > 0.0f) ? __fdividef(2.0f*dc_up, dc_safe + dc_up) : 0.0f;
    return f_low + phi*(f_high - f_low);
}

// ---------------- K1: advection + diffusion ----------------
__global__ void k_step(const float* __restrict__ dtp, int par){
    int idx  = blockIdx.x*256 + threadIdx.x;
    int j    = idx & 255;
    int i    = (idx >> 8) & 255;
    int base = idx & ~0xFFFF;

    const float dt   = __ldg(dtp);
    const float dtdx = dt * INVDX;

    const float* __restrict__ dfld = par ? g_d1 : g_d0;
    float*       __restrict__ dout = par ? g_d0 : g_d1;

    int im2 = ((i-2)&255)<<8, im1 = ((i-1)&255)<<8, i0 = i<<8,
        ip1 = ((i+1)&255)<<8, ip2 = ((i+2)&255)<<8;
    int jm2 = (j-2)&255, jm1 = (j-1)&255, jp1 = (j+1)&255, jp2 = (j+2)&255;

    float u_im2 = __ldg(&g_u[base+im2+j]);
    float u_im1 = __ldg(&g_u[base+im1+j]);
    float u_c   = __ldg(&g_u[base+i0 +j]);
    float u_ip1 = __ldg(&g_u[base+ip1+j]);
    float u_ip2 = __ldg(&g_u[base+ip2+j]);
    float u_jm2 = __ldg(&g_u[base+i0+jm2]);
    float u_jm1 = __ldg(&g_u[base+i0+jm1]);
    float u_jp1 = __ldg(&g_u[base+i0+jp1]);
    float u_jp2 = __ldg(&g_u[base+i0+jp2]);

    float v_im2 = __ldg(&g_v[base+im2+j]);
    float v_im1 = __ldg(&g_v[base+im1+j]);
    float v_c   = __ldg(&g_v[base+i0 +j]);
    float v_ip1 = __ldg(&g_v[base+ip1+j]);
    float v_ip2 = __ldg(&g_v[base+ip2+j]);
    float v_jm2 = __ldg(&g_v[base+i0+jm2]);
    float v_jm1 = __ldg(&g_v[base+i0+jm1]);
    float v_jp1 = __ldg(&g_v[base+i0+jp1]);
    float v_jp2 = __ldg(&g_v[base+i0+jp2]);

    float d_im2 = __ldg(&dfld[base+im2+j]);
    float d_im1 = __ldg(&dfld[base+im1+j]);
    float d_c   = __ldg(&dfld[base+i0 +j]);
    float d_ip1 = __ldg(&dfld[base+ip1+j]);
    float d_ip2 = __ldg(&dfld[base+ip2+j]);
    float d_jm2 = __ldg(&dfld[base+i0+jm2]);
    float d_jm1 = __ldg(&dfld[base+i0+jm1]);
    float d_jp1 = __ldg(&dfld[base+i0+jp1]);
    float d_jp2 = __ldg(&dfld[base+i0+jp2]);

    float uf_p = 0.5f*(u_c   + u_ip1);
    float uf_m = 0.5f*(u_im1 + u_c  );
    float vf_p = 0.5f*(v_c   + v_jp1);
    float vf_m = 0.5f*(v_jm1 + v_c  );

    {
        float Fip = face_flux(u_im1, u_c,   u_ip1, u_ip2, uf_p, dtdx);
        float Fim = face_flux(u_im2, u_im1, u_c,   u_ip1, uf_m, dtdx);
        float Fjp = face_flux(u_jm1, u_c,   u_jp1, u_jp2, vf_p, dtdx);
        float Fjm = face_flux(u_jm2, u_jm1, u_c,   u_jp1, vf_m, dtdx);
        float tend = -((Fip - Fim) + (Fjp - Fjm)) * INVDX;
        float lap  = (u_im1 + u_ip1 + u_jm1 + u_jp1 - 4.0f*u_c) * INVDX2;
        g_u1[idx] = u_c + dt*(tend + VISCF*lap);
    }
    {
        float Fip = face_flux(v_im1, v_c,   v_ip1, v_ip2, uf_p, dtdx);
        float Fim = face_flux(v_im2, v_im1, v_c,   v_ip1, uf_m, dtdx);
        float Fjp = face_flux(v_jm1, v_c,   v_jp1, v_jp2, vf_p, dtdx);
        float Fjm = face_flux(v_jm2, v_jm1, v_c,   v_jp1, vf_m, dtdx);
        float tend = -((Fip - Fim) + (Fjp - Fjm)) * INVDX;
        float lap  = (v_im1 + v_ip1 + v_jm1 + v_jp1 - 4.0f*v_c) * INVDX2;
        g_v1[idx] = v_c + dt*(tend + VISCF*lap);
    }
    {
        float Fip = face_flux(d_im1, d_c,   d_ip1, d_ip2, uf_p, dtdx);
        float Fim = face_flux(d_im2, d_im1, d_c,   d_ip1, uf_m, dtdx);
        float Fjp = face_flux(d_jm1, d_c,   d_jp1, d_jp2, vf_p, dtdx);
        float Fjm = face_flux(d_jm2, d_jm1, d_c,   d_jp1, vf_m, dtdx);
        float tend = -((Fip - Fim) + (Fjp - Fjm)) * INVDX;
        dout[idx] = d_c + dt*tend;
    }
}

// ---------------- K2: divergence + paired real row FFT (r2c), one warp per row pair ----------------
__global__ void k_divfft(){
    __shared__ float2 sm[8][256];
    int tid = threadIdx.x, wid = tid >> 5, lane = tid & 31;
    int fftid = blockIdx.x*8 + wid;       // 0..1023
    int b  = fftid >> 7;
    int mp = fftid & 127;
    int r0 = 2*mp, r1 = r0+1;
    int base = b << 16;
    int row0 = base + (r0<<8), rowm = base + (((r0-1)&255)<<8), row1 = base + (r1<<8);
    float2 v[8];
    #pragma unroll
    for (int m = 0; m < 8; m++){
        int jj = lane + 32*m;
        int jm = (jj-1)&255;
        float du0 = g_u1[row0+jj] - g_u1[rowm+jj];
        float dv0 = g_v1[row0+jj] - g_v1[row0+jm];
        float du1 = g_u1[row1+jj] - g_u1[row0+jj];
        float dv1 = g_v1[row1+jj] - g_v1[row1+jm];
        v[m] = make_float2((du0+dv0)*INVDX, (du1+dv1)*INVDX);
    }
    warp_fft256<-1>(v, lane);
    int br = __brev(lane) >> 27;
    #pragma unroll
    for (int j = 0; j < 8; j++) sm[wid][j + 8*br] = v[j];
    __syncwarp();
    int gb0 = (b*NG + r0)*K2P;
    int gb1 = (b*NG + r1)*K2P;
    #pragma unroll
    for (int m = 0; m < 4; m++){
        int k = lane + 32*m;               // 0..127
        float2 Z  = sm[wid][k];
        float2 Zn = sm[wid][(256-k)&255];
        g_G[gb0+k] = make_float2(0.5f*(Z.x+Zn.x), 0.5f*(Z.y-Zn.y));
        g_G[gb1+k] = make_float2(0.5f*(Z.y+Zn.y), 0.5f*(Zn.x-Z.x));
    }
    if (lane == 0){
        float2 Z = sm[wid][128];
        g_G[gb0+128] = make_float2(Z.x, 0.f);
        g_G[gb1+128] = make_float2(Z.y, 0.f);
    }
}

// ---------------- K3: column FFT * inv_lam * inverse column FFT, one warp per (k2,batch) ----------------
__global__ void k_colsolve(){
    __shared__ float2 sm[8][256];
    int tid = threadIdx.x, wid = tid >> 5, lane = tid & 31;
    int k2 = blockIdx.x;                  // 0..128
    int b  = wid;                         // 8 warps = 8 batches
    int gb = (b*NG)*K2P + k2;
    float2 v[8];
    #pragma unroll
    for (int m = 0; m < 8; m++) v[m] = g_G[gb + (lane + 32*m)*K2P];
    warp_fft256<-1>(v, lane);
    int br = __brev(lane) >> 27;
    float l2v = g_lam1[k2];
    #pragma unroll
    for (int j = 0; j < 8; j++){
        int k1 = j + 8*br;
        float sc = __fdividef(ONE65536, g_lam1[k1] + l2v);
        if ((k1 | k2) == 0) sc = 0.f;
        v[j].x *= sc; v[j].y *= sc;
        sm[wid][k1] = v[j];
    }
    __syncwarp();
    #pragma unroll
    for (int m = 0; m < 8; m++) v[m] = sm[wid][lane + 32*m];
    warp_fft256<1>(v, lane);
    #pragma unroll
    for (int j = 0; j < 8; j++){
        int i = j + 8*br;
        g_G[gb + i*K2P] = v[j];
    }
}

// ---------------- K4: paired inverse row FFT (c2r) -> q, one warp per row pair ----------------
__global__ void k_rowifft(){
    int tid = threadIdx.x, wid = tid >> 5, lane = tid & 31;
    int fftid = blockIdx.x*8 + wid;
    int b  = fftid >> 7;
    int mp = fftid & 127;
    int r0 = 2*mp, r1 = r0+1;
    int gb0 = (b*NG + r0)*K2P;
    int gb1 = (b*NG + r1)*K2P;
    float2 v[8];
    #pragma unroll
    for (int m = 0; m < 8; m++){
        int k = lane + 32*m;
        float2 W;
        if (k <= 128){
            float2 B0 = g_G[gb0+k], B1 = g_G[gb1+k];
            W = make_float2(B0.x - B1.y, B0.y + B1.x);
        } else {
            int kp = 256 - k;
            float2 B0 = g_G[gb0+kp], B1 = g_G[gb1+kp];
            W = make_float2(B0.x + B1.y, B1.x - B0.y);
        }
        v[m] = W;
    }
    warp_fft256<1>(v, lane);
    int br = __brev(lane) >> 27;
    int q0 = (b<<16) + (r0<<8) + 8*br;
    int q1 = (b<<16) + (r1<<8) + 8*br;
    float4 a0 = make_float4(v[0].x, v[1].x, v[2].x, v[3].x);
    float4 a1 = make_float4(v[4].x, v[5].x, v[6].x, v[7].x);
    float4 c0 = make_float4(v[0].y, v[1].y, v[2].y, v[3].y);
    float4 c1 = make_float4(v[4].y, v[5].y, v[6].y, v[7].y);
    *(float4*)&g_q[q0]     = a0;
    *(float4*)&g_q[q0 + 4] = a1;
    *(float4*)&g_q[q1]     = c0;
    *(float4*)&g_q[q1 + 4] = c1;
}

// ---------------- K5: projection correction (+ optional output write) ----------------
__global__ void k_correct(float* __restrict__ out, int par_new, int tstep, int wout){
    int idx  = blockIdx.x*256 + threadIdx.x;
    int j    = idx & 255;
    int i    = (idx >> 8) & 255;
    int base = idx & ~0xFFFF;
    int i0   = i << 8;
    int ip1  = ((i + 1) & 255) << 8;
    int jp1  = (j + 1) & 255;

    float qc  = g_q[idx];
    float qip = g_q[base + ip1 + j];
    float qjp = g_q[base + i0 + jp1];

    float un = g_u1[idx] - (qip - qc) * INVDX;
    float vn = g_v1[idx] - (qjp - qc) * INVDX;
    g_u[idx] = un;
    g_v[idx] = vn;

    if (wout){
        const float* __restrict__ dnew = par_new ? g_d1 : g_d0;
        float dd = dnew[idx];
        int b  = idx >> 16;
        int ij = idx & 0xFFFF;
        size_t o = ((size_t)b * TSTEPS + (size_t)tstep) * (size_t)(NG*NG*3) + (size_t)ij * 3;
        out[o + 0] = un;
        out[o + 1] = vn;
        out[o + 2] = dd;
    }
}

// ---------------- launch ----------------
extern "C" void kernel_launch(void* const* d_in, const int* in_sizes, int n_in,
                              void* d_out, int out_size){
    const float* y0  = (const float*)d_in[0];
    const float* dtp = (const float*)d_in[1];
    float* out = (float*)d_out;

    k_tables<<<1, 256>>>();
    k_init<<<NPTS/256, 256>>>(y0);

    int par = 0;
    for (int t = 0; t < TSTEPS; t++){
        for (int k = 0; k < INNERS; k++){
            k_step<<<NPTS/256, 256>>>(dtp, par);
            k_divfft  <<<128, 256>>>();
            k_colsolve<<<129, 256>>>();
            k_rowifft <<<128, 256>>>();
            int par_new = par ^ 1;
            k_correct<<<NPTS/256, 256>>>(out, par_new, t, (k == INNERS-1) ? 1 : 0);
            par = par_new;
        }
    }
}

// round 6
// speedup vs baseline: 1.1623x; 1.1623x over previous
#include <cuda_runtime.h>
#include <math.h>

#define NG 256
#define NB 8
#define NPTS (NB*NG*NG)
#define TSTEPS 8
#define INNERS 10
#define K2P 132            // padded half-spectrum columns (0..128 used)

#define INVDX     40.743665431525205f        // 256/(2*pi)
#define INVDX2    (INVDX*INVDX)
#define VISCF     1e-3f
#define ONE65536  1.52587890625e-5f          // 1/65536

#define SPAD(i) ((i) + ((i)>>4))
#define FSZ 272

// ---------------- scratch (no allocation allowed) ----------------
__device__ float  g_uA[NPTS], g_uB[NPTS];    // u1 ping-pong (pre-projection)
__device__ float  g_vA[NPTS], g_vB[NPTS];
__device__ float  g_d0[NPTS], g_d1[NPTS];
__device__ float  g_q [NPTS];
__device__ float2 g_G [NB*NG*K2P];   // half-spectrum scratch, layout [b][i][k2]
__device__ float2 g_tw[64];          // exp(-2*pi*i*k/256), k<64
__device__ float  g_lam1[NG];        // FD laplacian 1D eigenvalues

// ---------------- tables ----------------
__global__ void k_tables(){
    int t = threadIdx.x;   // 256 threads
    if (t < 64){
        float s, c;
        sincospif(t*(1.0f/128.0f), &s, &c);
        g_tw[t] = make_float2(c, -s);
    }
    float sn = sinpif(t*(1.0f/256.0f));
    g_lam1[t] = -4.0f*sn*sn*INVDX2;
}

// ---------------- init: de-interleave y0, zero q ----------------
__global__ void k_init(const float* __restrict__ y0){
    int idx = blockIdx.x*256 + threadIdx.x;
    int b   = idx >> 16;
    int ij  = idx & 0xFFFF;
    const float* p = y0 + (size_t)b*(NG*NG*3) + (size_t)ij*3;
    g_uA[idx] = p[0];
    g_vA[idx] = p[1];
    g_d0[idx] = p[2];
    g_q [idx] = 0.0f;
}

// ---------------- van-Leer limited face flux ----------------
__device__ __forceinline__ float face_flux(float cm1, float c0, float c1, float c2,
                                           float uf, float dtdx){
    float dc     = c1 - c0;
    float f_low  = (uf >= 0.0f) ? uf*c0 : uf*c1;
    float f_high = uf*0.5f*(c0+c1) - 0.5f*uf*uf*dtdx*dc;
    float dc_up  = (uf >= 0.0f) ? (c0 - cm1) : (c2 - c1);
    float dc_safe = (fabsf(dc) > 1e-12f) ? dc : 1e-12f;
    float phi = (dc_up * dc_safe > 0.0f) ? __fdividef(2.0f*dc_up, dc_safe + dc_up) : 0.0f;
    return f_low + phi*(f_high - f_low);
}

// ---------------- K1: fused lazy-projection + advection + diffusion ----------------
// State entering: (u1p, v1p, q) with corrected velocity u = u1p - grad_q.
// Reconstructs corrected stencil values on the fly; writes new (u1, v1) pre-projection
// and advected density.
__global__ void k_stepF(const float* __restrict__ dtp, int dpar, int upar){
    int idx  = blockIdx.x*256 + threadIdx.x;
    int j    = idx & 255;
    int i    = (idx >> 8) & 255;
    int base = idx & ~0xFFFF;

    const float dt   = __ldg(dtp);
    const float dtdx = dt * INVDX;

    const float* __restrict__ up = upar ? g_uB : g_uA;
    const float* __restrict__ vp = upar ? g_vB : g_vA;
    float*       __restrict__ un = upar ? g_uA : g_uB;
    float*       __restrict__ vn = upar ? g_vA : g_vB;
    const float* __restrict__ dfld = dpar ? g_d1 : g_d0;
    float*       __restrict__ dout = dpar ? g_d0 : g_d1;

    int rm2 = ((i-2)&255)<<8, rm1 = ((i-1)&255)<<8, r0 = i<<8,
        rp1 = ((i+1)&255)<<8, rp2 = ((i+2)&255)<<8, rp3 = ((i+3)&255)<<8;
    int cm2 = (j-2)&255, cm1 = (j-1)&255, cp1 = (j+1)&255,
        cp2 = (j+2)&255, cp3 = (j+3)&255;

    // ---- q stencil (18 loads) ----
    float q_m2_0 = __ldg(&g_q[base+rm2+j]);
    float q_m1_0 = __ldg(&g_q[base+rm1+j]);
    float q_0_0  = __ldg(&g_q[base+r0 +j]);
    float q_p1_0 = __ldg(&g_q[base+rp1+j]);
    float q_p2_0 = __ldg(&g_q[base+rp2+j]);
    float q_p3_0 = __ldg(&g_q[base+rp3+j]);
    float q_m2_1 = __ldg(&g_q[base+rm2+cp1]);
    float q_m1_1 = __ldg(&g_q[base+rm1+cp1]);
    float q_0_1  = __ldg(&g_q[base+r0 +cp1]);
    float q_p1_1 = __ldg(&g_q[base+rp1+cp1]);
    float q_p2_1 = __ldg(&g_q[base+rp2+cp1]);
    float q_0_m2 = __ldg(&g_q[base+r0 +cm2]);
    float q_0_m1 = __ldg(&g_q[base+r0 +cm1]);
    float q_0_p2 = __ldg(&g_q[base+r0 +cp2]);
    float q_0_p3 = __ldg(&g_q[base+r0 +cp3]);
    float q_1_m2 = __ldg(&g_q[base+rp1+cm2]);
    float q_1_m1 = __ldg(&g_q[base+rp1+cm1]);
    float q_1_p2 = __ldg(&g_q[base+rp1+cp2]);

    // ---- corrected u stencil ----
    float u_im2 = __ldg(&up[base+rm2+j])   - (q_m1_0 - q_m2_0)*INVDX;
    float u_im1 = __ldg(&up[base+rm1+j])   - (q_0_0  - q_m1_0)*INVDX;
    float u_c   = __ldg(&up[base+r0 +j])   - (q_p1_0 - q_0_0 )*INVDX;
    float u_ip1 = __ldg(&up[base+rp1+j])   - (q_p2_0 - q_p1_0)*INVDX;
    float u_ip2 = __ldg(&up[base+rp2+j])   - (q_p3_0 - q_p2_0)*INVDX;
    float u_jm2 = __ldg(&up[base+r0+cm2])  - (q_1_m2 - q_0_m2)*INVDX;
    float u_jm1 = __ldg(&up[base+r0+cm1])  - (q_1_m1 - q_0_m1)*INVDX;
    float u_jp1 = __ldg(&up[base+r0+cp1])  - (q_p1_1 - q_0_1 )*INVDX;
    float u_jp2 = __ldg(&up[base+r0+cp2])  - (q_1_p2 - q_0_p2)*INVDX;

    // ---- corrected v stencil ----
    float v_im2 = __ldg(&vp[base+rm2+j])   - (q_m2_1 - q_m2_0)*INVDX;
    float v_im1 = __ldg(&vp[base+rm1+j])   - (q_m1_1 - q_m1_0)*INVDX;
    float v_c   = __ldg(&vp[base+r0 +j])   - (q_0_1  - q_0_0 )*INVDX;
    float v_ip1 = __ldg(&vp[base+rp1+j])   - (q_p1_1 - q_p1_0)*INVDX;
    float v_ip2 = __ldg(&vp[base+rp2+j])   - (q_p2_1 - q_p2_0)*INVDX;
    float v_jm2 = __ldg(&vp[base+r0+cm2])  - (q_0_m1 - q_0_m2)*INVDX;
    float v_jm1 = __ldg(&vp[base+r0+cm1])  - (q_0_0  - q_0_m1)*INVDX;
    float v_jp1 = __ldg(&vp[base+r0+cp1])  - (q_0_p2 - q_0_1 )*INVDX;
    float v_jp2 = __ldg(&vp[base+r0+cp2])  - (q_0_p3 - q_0_p2)*INVDX;

    // ---- density stencil ----
    float d_im2 = __ldg(&dfld[base+rm2+j]);
    float d_im1 = __ldg(&dfld[base+rm1+j]);
    float d_c   = __ldg(&dfld[base+r0 +j]);
    float d_ip1 = __ldg(&dfld[base+rp1+j]);
    float d_ip2 = __ldg(&dfld[base+rp2+j]);
    float d_jm2 = __ldg(&dfld[base+r0+cm2]);
    float d_jm1 = __ldg(&dfld[base+r0+cm1]);
    float d_jp1 = __ldg(&dfld[base+r0+cp1]);
    float d_jp2 = __ldg(&dfld[base+r0+cp2]);

    float uf_p = 0.5f*(u_c   + u_ip1);
    float uf_m = 0.5f*(u_im1 + u_c  );
    float vf_p = 0.5f*(v_c   + v_jp1);
    float vf_m = 0.5f*(v_jm1 + v_c  );

    {
        float Fip = face_flux(u_im1, u_c,   u_ip1, u_ip2, uf_p, dtdx);
        float Fim = face_flux(u_im2, u_im1, u_c,   u_ip1, uf_m, dtdx);
        float Fjp = face_flux(u_jm1, u_c,   u_jp1, u_jp2, vf_p, dtdx);
        float Fjm = face_flux(u_jm2, u_jm1, u_c,   u_jp1, vf_m, dtdx);
        float tend = -((Fip - Fim) + (Fjp - Fjm)) * INVDX;
        float lap  = (u_im1 + u_ip1 + u_jm1 + u_jp1 - 4.0f*u_c) * INVDX2;
        un[idx] = u_c + dt*(tend + VISCF*lap);
    }
    {
        float Fip = face_flux(v_im1, v_c,   v_ip1, v_ip2, uf_p, dtdx);
        float Fim = face_flux(v_im2, v_im1, v_c,   v_ip1, uf_m, dtdx);
        float Fjp = face_flux(v_jm1, v_c,   v_jp1, v_jp2, vf_p, dtdx);
        float Fjm = face_flux(v_jm2, v_jm1, v_c,   v_jp1, vf_m, dtdx);
        float tend = -((Fip - Fim) + (Fjp - Fjm)) * INVDX;
        float lap  = (v_im1 + v_ip1 + v_jm1 + v_jp1 - 4.0f*v_c) * INVDX2;
        vn[idx] = v_c + dt*(tend + VISCF*lap);
    }
    {
        float Fip = face_flux(d_im1, d_c,   d_ip1, d_ip2, uf_p, dtdx);
        float Fim = face_flux(d_im2, d_im1, d_c,   d_ip1, uf_m, dtdx);
        float Fjp = face_flux(d_jm1, d_c,   d_jp1, d_jp2, vf_p, dtdx);
        float Fjm = face_flux(d_jm2, d_jm1, d_c,   d_jp1, vf_m, dtdx);
        float tend = -((Fip - Fim) + (Fjp - Fjm)) * INVDX;
        dout[idx] = d_c + dt*tend;
    }
}

// ---------------- radix-4 Stockham 256-pt FFT (64 threads per transform) ----------------
__device__ __forceinline__ float2 cmulf(float2 a, float2 b){
    return make_float2(fmaf(a.x, b.x, -a.y*b.y), fmaf(a.x, b.y, a.y*b.x));
}

template<bool INV>
__device__ __forceinline__ float2* fft256_r4(float2* sA, float2* sB, const float2* tw, int t){
    float2* src = sA; float2* dst = sB;
    #pragma unroll
    for (int st = 0; st < 4; st++){
        int s  = 1 << (2*st);
        int q  = t & (s-1);
        int sp = t - q;                    // s*p
        float2 a = src[SPAD(t)];
        float2 b = src[SPAD(t+64)];
        float2 c = src[SPAD(t+128)];
        float2 d = src[SPAD(t+192)];
        float2 w1 = tw[sp];
        if (INV) w1.y = -w1.y;
        float2 w2 = make_float2(w1.x*w1.x - w1.y*w1.y, 2.0f*w1.x*w1.y);
        float2 w3 = cmulf(w1, w2);
        float2 t0 = make_float2(a.x+c.x, a.y+c.y);
        float2 t1 = make_float2(a.x-c.x, a.y-c.y);
        float2 t2 = make_float2(b.x+d.x, b.y+d.y);
        float2 t3 = make_float2(b.x-d.x, b.y-d.y);
        float2 y0 = make_float2(t0.x+t2.x, t0.y+t2.y);
        float2 y2 = make_float2(t0.x-t2.x, t0.y-t2.y);
        float2 u1, u3;
        if (!INV){
            u1 = make_float2(t1.x + t3.y, t1.y - t3.x);
            u3 = make_float2(t1.x - t3.y, t1.y + t3.x);
        } else {
            u1 = make_float2(t1.x - t3.y, t1.y + t3.x);
            u3 = make_float2(t1.x + t3.y, t1.y - t3.x);
        }
        int o = 4*sp + q;
        dst[SPAD(o)]       = y0;
        dst[SPAD(o + s)]   = cmulf(w1, u1);
        dst[SPAD(o + 2*s)] = cmulf(w2, y2);
        dst[SPAD(o + 3*s)] = cmulf(w3, u3);
        __syncthreads();
        float2* tmp = src; src = dst; dst = tmp;
    }
    return src;
}

// ---------------- K2: divergence + paired real row FFT (r2c) ----------------
__global__ void k_divfft(int upar){
    __shared__ float2 sA[4][FSZ], sB[4][FSZ];
    __shared__ float2 stw[64];
    const float* __restrict__ u1 = upar ? g_uB : g_uA;
    const float* __restrict__ v1 = upar ? g_vB : g_vA;
    int tid = threadIdx.x;                // 256
    int f = tid >> 6, t = tid & 63;
    if (tid < 64) stw[tid] = g_tw[tid];
    int b  = blockIdx.y;
    int mp = blockIdx.x*4 + f;            // row pair 0..127
    int r0 = mp*2, r1 = r0+1;
    int base = b << 16;
    int row0 = base + (r0<<8);
    int rowm = base + (((r0-1)&255)<<8);
    int row1 = base + (r1<<8);
    #pragma unroll
    for (int m = 0; m < 4; m++){
        int j  = t + 64*m;
        int jm = (j-1)&255;
        float du0 = u1[row0+j] - u1[rowm+j];
        float dv0 = v1[row0+j] - v1[row0+jm];
        float du1 = u1[row1+j] - u1[row0+j];
        float dv1 = v1[row1+j] - v1[row1+jm];
        sA[f][SPAD(j)] = make_float2((du0+dv0)*INVDX, (du1+dv1)*INVDX);
    }
    __syncthreads();
    float2* res = fft256_r4<false>(sA[f], sB[f], stw, t);
    int gb0 = (b*NG + r0)*K2P;
    int gb1 = (b*NG + r1)*K2P;
    #pragma unroll
    for (int m = 0; m < 3; m++){
        int k = t + 64*m;
        if (k <= 128){
            float2 Z  = res[SPAD(k)];
            float2 Zn = res[SPAD((256-k)&255)];
            g_G[gb0 + k] = make_float2(0.5f*(Z.x+Zn.x), 0.5f*(Z.y-Zn.y));
            g_G[gb1 + k] = make_float2(0.5f*(Z.y+Zn.y), 0.5f*(Zn.x-Z.x));
        }
    }
}

// ---------------- K3: column FFT * inv_lam * inverse column FFT ----------------
__global__ void k_colsolve(){
    __shared__ float2 sA[4][FSZ], sB[4][FSZ];
    __shared__ float2 stw[64];
    int tid = threadIdx.x;                // 256
    int c = tid & 3, t = tid >> 2;
    if (tid < 64) stw[tid] = g_tw[tid];
    int b  = blockIdx.y;
    int k2 = blockIdx.x*4 + c;            // 0..131 (129..131 are pad)
    int gb = b*NG*K2P + k2;
    #pragma unroll
    for (int m = 0; m < 4; m++){
        int i = t + 64*m;
        sA[c][SPAD(i)] = g_G[gb + i*K2P];
    }
    __syncthreads();
    float2* res = fft256_r4<false>(sA[c], sB[c], stw, t);
    float l2v = g_lam1[k2 & 255];
    #pragma unroll
    for (int m = 0; m < 4; m++){
        int k1 = t + 64*m;
        float sc = __fdividef(ONE65536, g_lam1[k1] + l2v);
        if ((k1 | k2) == 0) sc = 0.0f;
        float2 vz = res[SPAD(k1)];
        res[SPAD(k1)] = make_float2(vz.x*sc, vz.y*sc);
    }
    __syncthreads();
    float2* res2 = fft256_r4<true>(sA[c], sB[c], stw, t);
    #pragma unroll
    for (int m = 0; m < 4; m++){
        int i = t + 64*m;
        g_G[gb + i*K2P] = res2[SPAD(i)];
    }
}

// ---------------- K4: paired inverse row FFT (c2r) -> q ----------------
__global__ void k_rowifft(){
    __shared__ float2 sA[4][FSZ], sB[4][FSZ];
    __shared__ float2 stw[64];
    int tid = threadIdx.x;                // 256
    int f = tid >> 6, t = tid & 63;
    if (tid < 64) stw[tid] = g_tw[tid];
    int b  = blockIdx.y;
    int mp = blockIdx.x*4 + f;
    int r0 = 2*mp, r1 = r0+1;
    int gb0 = (b*NG + r0)*K2P;
    int gb1 = (b*NG + r1)*K2P;
    #pragma unroll
    for (int m = 0; m < 4; m++){
        int k = t + 64*m;
        float2 W;
        if (k <= 128){
            float2 B0 = g_G[gb0 + k];
            float2 B1 = g_G[gb1 + k];
            W = make_float2(B0.x - B1.y, B0.y + B1.x);
        } else {
            int kp = 256 - k;
            float2 B0 = g_G[gb0 + kp];
            float2 B1 = g_G[gb1 + kp];
            W = make_float2(B0.x + B1.y, B1.x - B0.y);
        }
        sA[f][SPAD(k)] = W;
    }
    __syncthreads();
    float2* res = fft256_r4<true>(sA[f], sB[f], stw, t);
    int q0 = (b<<16) + (r0<<8);
    int q1 = (b<<16) + (r1<<8);
    #pragma unroll
    for (int m = 0; m < 4; m++){
        int j = t + 64*m;
        float2 z = res[SPAD(j)];
        g_q[q0 + j] = z.x;
        g_q[q1 + j] = z.y;
    }
}

// ---------------- K5 (per outer step): corrected state -> output slice ----------------
__global__ void k_out(float* __restrict__ out, int tstep, int uparNew, int dparNew){
    int idx  = blockIdx.x*256 + threadIdx.x;
    int j    = idx & 255;
    int i    = (idx >> 8) & 255;
    int base = idx & ~0xFFFF;
    int i0   = i << 8;
    int ip1  = ((i + 1) & 255) << 8;
    int jp1  = (j + 1) & 255;

    const float* __restrict__ u1 = uparNew ? g_uB : g_uA;
    const float* __restrict__ v1 = uparNew ? g_vB : g_vA;
    const float* __restrict__ dn = dparNew ? g_d1 : g_d0;

    float qc  = g_q[idx];
    float qip = g_q[base + ip1 + j];
    float qjp = g_q[base + i0 + jp1];

    float un = u1[idx] - (qip - qc) * INVDX;
    float vn = v1[idx] - (qjp - qc) * INVDX;
    float dd = dn[idx];

    int b  = idx >> 16;
    int ij = idx & 0xFFFF;
    size_t o = ((size_t)b * TSTEPS + (size_t)tstep) * (size_t)(NG*NG*3) + (size_t)ij * 3;
    out[o + 0] = un;
    out[o + 1] = vn;
    out[o + 2] = dd;
}

// ---------------- launch ----------------
extern "C" void kernel_launch(void* const* d_in, const int* in_sizes, int n_in,
                              void* d_out, int out_size){
    const float* y0  = (const float*)d_in[0];
    const float* dtp = (const float*)d_in[1];
    float* out = (float*)d_out;

    k_tables<<<1, 256>>>();
    k_init<<<NPTS/256, 256>>>(y0);

    int upar = 0;   // current u1 in A; q starts at 0 (so corrected == u1)
    int dpar = 0;   // current density in d0
    for (int t = 0; t < TSTEPS; t++){
        for (int k = 0; k < INNERS; k++){
            k_stepF<<<NPTS/256, 256>>>(dtp, dpar, upar);
            int uparNew = upar ^ 1;
            int dparNew = dpar ^ 1;
            k_divfft  <<<dim3(32, NB), 256>>>(uparNew);
            k_colsolve<<<dim3(33, NB), 256>>>();
            k_rowifft <<<dim3(32, NB), 256>>>();
            if (k == INNERS-1)
                k_out<<<NPTS/256, 256>>>(out, t, uparNew, dparNew);
            upar = uparNew;
            dpar = dparNew;
        }
    }
}

// round 7
// speedup vs baseline: 1.2506x; 1.0759x over previous
#include <cuda_runtime.h>
#include <math.h>

#define NG 256
#define NB 8
#define NPTS (NB*NG*NG)
#define TSTEPS 8
#define INNERS 10
#define K2P 132            // padded half-spectrum columns (0..128 used)

#define INVDX     40.743665431525205f        // 256/(2*pi)
#define INVDX2    (INVDX*INVDX)
#define VISCF     1e-3f
#define ONE65536  1.52587890625e-5f          // 1/65536

#define C16f 0.92387953251128674f            // cos(pi/8)
#define S16f 0.38268343236508978f            // sin(pi/8)
#define RQ2f 0.70710678118654752f            // sqrt(2)/2

// ---------------- scratch (no allocation allowed) ----------------
__device__ float  g_uA[NPTS], g_uB[NPTS];    // u1 ping-pong (pre-projection)
__device__ float  g_vA[NPTS], g_vB[NPTS];
__device__ float  g_d0[NPTS], g_d1[NPTS];
__device__ float  g_q [NPTS];
__device__ float2 g_G [NB*NG*K2P];   // half-spectrum scratch, layout [b][i][k2]
__device__ float2 g_twf[256];        // exp(-2*pi*i*m/256), m=0..255
__device__ float  g_lam1[NG];        // FD laplacian 1D eigenvalues

// ---------------- tables ----------------
__global__ void k_tables(){
    int t = threadIdx.x;   // 256 threads
    float s, c;
    sincospif(t*(1.0f/128.0f), &s, &c);
    g_twf[t] = make_float2(c, -s);
    float sn = sinpif(t*(1.0f/256.0f));
    g_lam1[t] = -4.0f*sn*sn*INVDX2;
}

// ---------------- init: de-interleave y0, zero q ----------------
__global__ void k_init(const float* __restrict__ y0){
    int idx = blockIdx.x*256 + threadIdx.x;
    int b   = idx >> 16;
    int ij  = idx & 0xFFFF;
    const float* p = y0 + (size_t)b*(NG*NG*3) + (size_t)ij*3;
    g_uA[idx] = p[0];
    g_vA[idx] = p[1];
    g_d0[idx] = p[2];
    g_q [idx] = 0.0f;
}

// ---------------- complex helpers ----------------
__device__ __forceinline__ float2 cadd(float2 a, float2 b){ return make_float2(a.x+b.x, a.y+b.y); }
__device__ __forceinline__ float2 csub(float2 a, float2 b){ return make_float2(a.x-b.x, a.y-b.y); }
__device__ __forceinline__ float2 cmulf(float2 a, float2 b){
    return make_float2(fmaf(a.x,b.x,-a.y*b.y), fmaf(a.x,b.y,a.y*b.x));
}

// ---------------- radix-4 butterfly (S=-1 fwd, S=+1 inv), in place ----------------
template<int S>
__device__ __forceinline__ void dft4(float2&a, float2&b, float2&c, float2&d){
    float2 t0=cadd(a,c), t1=csub(a,c), t2=cadd(b,d), t3=csub(b,d);
    a = cadd(t0,t2);
    c = csub(t0,t2);
    if (S < 0){
        b = make_float2(t1.x + t3.y, t1.y - t3.x);   // t1 - i t3
        d = make_float2(t1.x - t3.y, t1.y + t3.x);   // t1 + i t3
    } else {
        b = make_float2(t1.x - t3.y, t1.y + t3.x);
        d = make_float2(t1.x + t3.y, t1.y - t3.x);
    }
}

// W16^e constants as (cos, sin); forward uses (c,-s), inverse (c,s)
template<int S>
__device__ __forceinline__ float2 tw16(float cx, float sx){
    return make_float2(cx, (S<0) ? -sx : sx);
}

// ---------------- 16-point DFT fully in registers ----------------
// input x[n] (natural order), output x[k] (natural order)
template<int S>
__device__ __forceinline__ void dft16(float2 x[16]){
    float2 Y0a=x[0], Y0b=x[4], Y0c=x[8],  Y0d=x[12];
    float2 Y1a=x[1], Y1b=x[5], Y1c=x[9],  Y1d=x[13];
    float2 Y2a=x[2], Y2b=x[6], Y2c=x[10], Y2d=x[14];
    float2 Y3a=x[3], Y3b=x[7], Y3c=x[11], Y3d=x[15];
    dft4<S>(Y0a,Y0b,Y0c,Y0d);
    dft4<S>(Y1a,Y1b,Y1c,Y1d);
    dft4<S>(Y2a,Y2b,Y2c,Y2d);
    dft4<S>(Y3a,Y3b,Y3c,Y3d);
    // twiddles W16^{b*k0}
    Y1b = cmulf(Y1b, tw16<S>( C16f, S16f));   // e=1
    Y1c = cmulf(Y1c, tw16<S>( RQ2f, RQ2f));   // e=2
    Y1d = cmulf(Y1d, tw16<S>( S16f, C16f));   // e=3
    Y2b = cmulf(Y2b, tw16<S>( RQ2f, RQ2f));   // e=2
    Y2c = (S<0) ? make_float2( Y2c.y, -Y2c.x) : make_float2(-Y2c.y,  Y2c.x);  // e=4: *(-+i)
    Y2d = cmulf(Y2d, tw16<S>(-RQ2f, RQ2f));   // e=6
    Y3b = cmulf(Y3b, tw16<S>( S16f, C16f));   // e=3
    Y3c = cmulf(Y3c, tw16<S>(-RQ2f, RQ2f));   // e=6
    Y3d = cmulf(Y3d, tw16<S>(-C16f,-S16f));   // e=9
    // final radix-4 over b for each k0; X[k0 + 4 k1]
    {   float2 a=Y0a,b=Y1a,c=Y2a,d=Y3a; dft4<S>(a,b,c,d);
        x[0]=a; x[4]=b; x[8]=c; x[12]=d; }
    {   float2 a=Y0b,b=Y1b,c=Y2b,d=Y3b; dft4<S>(a,b,c,d);
        x[1]=a; x[5]=b; x[9]=c; x[13]=d; }
    {   float2 a=Y0c,b=Y1c,c=Y2c,d=Y3c; dft4<S>(a,b,c,d);
        x[2]=a; x[6]=b; x[10]=c; x[14]=d; }
    {   float2 a=Y0d,b=Y1d,c=Y2d,d=Y3d; dft4<S>(a,b,c,d);
        x[3]=a; x[7]=b; x[11]=c; x[15]=d; }
}

// ---------------- four-step 256-pt FFT core ----------------
// Thread t of a 16-thread FFT group holds x[n1] = data[16*n1 + t] on entry.
// On exit, thread t holds x[k2] = X[t + 16*k2].
// BS: true -> block-wide sync (FFT spans warps), false -> warp-local sync.
template<int S, bool BS>
__device__ __forceinline__ void fftcore(float2 x[16], int t, float2* tbf, const float2* stw){
    dft16<S>(x);
    #pragma unroll
    for (int k1 = 1; k1 < 16; k1++){
        float2 w = stw[t*k1];
        if (S > 0) w.y = -w.y;
        x[k1] = cmulf(x[k1], w);
    }
    #pragma unroll
    for (int k1 = 0; k1 < 16; k1++) tbf[t*17 + k1] = x[k1];
    if (BS) __syncthreads(); else __syncwarp();
    #pragma unroll
    for (int n2 = 0; n2 < 16; n2++) x[n2] = tbf[n2*17 + t];
    dft16<S>(x);
}

// ---------------- van-Leer limited face flux ----------------
__device__ __forceinline__ float face_flux(float cm1, float c0, float c1, float c2,
                                           float uf, float dtdx){
    float dc     = c1 - c0;
    float f_low  = (uf >= 0.0f) ? uf*c0 : uf*c1;
    float f_high = uf*0.5f*(c0+c1) - 0.5f*uf*uf*dtdx*dc;
    float dc_up  = (uf >= 0.0f) ? (c0 - cm1) : (c2 - c1);
    float dc_safe = (fabsf(dc) > 1e-12f) ? dc : 1e-12f;
    float phi = (dc_up * dc_safe > 0.0f) ? __fdividef(2.0f*dc_up, dc_safe + dc_up) : 0.0f;
    return f_low + phi*(f_high - f_low);
}

// ---------------- K1: fused lazy-projection + advection + diffusion ----------------
__global__ void k_stepF(const float* __restrict__ dtp, int dpar, int upar){
    int idx  = blockIdx.x*256 + threadIdx.x;
    int j    = idx & 255;
    int i    = (idx >> 8) & 255;
    int base = idx & ~0xFFFF;

    const float dt   = __ldg(dtp);
    const float dtdx = dt * INVDX;

    const float* __restrict__ up = upar ? g_uB : g_uA;
    const float* __restrict__ vp = upar ? g_vB : g_vA;
    float*       __restrict__ un = upar ? g_uA : g_uB;
    float*       __restrict__ vn = upar ? g_vA : g_vB;
    const float* __restrict__ dfld = dpar ? g_d1 : g_d0;
    float*       __restrict__ dout = dpar ? g_d0 : g_d1;

    int rm2 = ((i-2)&255)<<8, rm1 = ((i-1)&255)<<8, r0 = i<<8,
        rp1 = ((i+1)&255)<<8, rp2 = ((i+2)&255)<<8, rp3 = ((i+3)&255)<<8;
    int cm2 = (j-2)&255, cm1 = (j-1)&255, cp1 = (j+1)&255,
        cp2 = (j+2)&255, cp3 = (j+3)&255;

    float q_m2_0 = __ldg(&g_q[base+rm2+j]);
    float q_m1_0 = __ldg(&g_q[base+rm1+j]);
    float q_0_0  = __ldg(&g_q[base+r0 +j]);
    float q_p1_0 = __ldg(&g_q[base+rp1+j]);
    float q_p2_0 = __ldg(&g_q[base+rp2+j]);
    float q_p3_0 = __ldg(&g_q[base+rp3+j]);
    float q_m2_1 = __ldg(&g_q[base+rm2+cp1]);
    float q_m1_1 = __ldg(&g_q[base+rm1+cp1]);
    float q_0_1  = __ldg(&g_q[base+r0 +cp1]);
    float q_p1_1 = __ldg(&g_q[base+rp1+cp1]);
    float q_p2_1 = __ldg(&g_q[base+rp2+cp1]);
    float q_0_m2 = __ldg(&g_q[base+r0 +cm2]);
    float q_0_m1 = __ldg(&g_q[base+r0 +cm1]);
    float q_0_p2 = __ldg(&g_q[base+r0 +cp2]);
    float q_0_p3 = __ldg(&g_q[base+r0 +cp3]);
    float q_1_m2 = __ldg(&g_q[base+rp1+cm2]);
    float q_1_m1 = __ldg(&g_q[base+rp1+cm1]);
    float q_1_p2 = __ldg(&g_q[base+rp1+cp2]);

    float u_im2 = __ldg(&up[base+rm2+j])   - (q_m1_0 - q_m2_0)*INVDX;
    float u_im1 = __ldg(&up[base+rm1+j])   - (q_0_0  - q_m1_0)*INVDX;
    float u_c   = __ldg(&up[base+r0 +j])   - (q_p1_0 - q_0_0 )*INVDX;
    float u_ip1 = __ldg(&up[base+rp1+j])   - (q_p2_0 - q_p1_0)*INVDX;
    float u_ip2 = __ldg(&up[base+rp2+j])   - (q_p3_0 - q_p2_0)*INVDX;
    float u_jm2 = __ldg(&up[base+r0+cm2])  - (q_1_m2 - q_0_m2)*INVDX;
    float u_jm1 = __ldg(&up[base+r0+cm1])  - (q_1_m1 - q_0_m1)*INVDX;
    float u_jp1 = __ldg(&up[base+r0+cp1])  - (q_p1_1 - q_0_1 )*INVDX;
    float u_jp2 = __ldg(&up[base+r0+cp2])  - (q_1_p2 - q_0_p2)*INVDX;

    float v_im2 = __ldg(&vp[base+rm2+j])   - (q_m2_1 - q_m2_0)*INVDX;
    float v_im1 = __ldg(&vp[base+rm1+j])   - (q_m1_1 - q_m1_0)*INVDX;
    float v_c   = __ldg(&vp[base+r0 +j])   - (q_0_1  - q_0_0 )*INVDX;
    float v_ip1 = __ldg(&vp[base+rp1+j])   - (q_p1_1 - q_p1_0)*INVDX;
    float v_ip2 = __ldg(&vp[base+rp2+j])   - (q_p2_1 - q_p2_0)*INVDX;
    float v_jm2 = __ldg(&vp[base+r0+cm2])  - (q_0_m1 - q_0_m2)*INVDX;
    float v_jm1 = __ldg(&vp[base+r0+cm1])  - (q_0_0  - q_0_m1)*INVDX;
    float v_jp1 = __ldg(&vp[base+r0+cp1])  - (q_0_p2 - q_0_1 )*INVDX;
    float v_jp2 = __ldg(&vp[base+r0+cp2])  - (q_0_p3 - q_0_p2)*INVDX;

    float d_im2 = __ldg(&dfld[base+rm2+j]);
    float d_im1 = __ldg(&dfld[base+rm1+j]);
    float d_c   = __ldg(&dfld[base+r0 +j]);
    float d_ip1 = __ldg(&dfld[base+rp1+j]);
    float d_ip2 = __ldg(&dfld[base+rp2+j]);
    float d_jm2 = __ldg(&dfld[base+r0+cm2]);
    float d_jm1 = __ldg(&dfld[base+r0+cm1]);
    float d_jp1 = __ldg(&dfld[base+r0+cp1]);
    float d_jp2 = __ldg(&dfld[base+r0+cp2]);

    float uf_p = 0.5f*(u_c   + u_ip1);
    float uf_m = 0.5f*(u_im1 + u_c  );
    float vf_p = 0.5f*(v_c   + v_jp1);
    float vf_m = 0.5f*(v_jm1 + v_c  );

    {
        float Fip = face_flux(u_im1, u_c,   u_ip1, u_ip2, uf_p, dtdx);
        float Fim = face_flux(u_im2, u_im1, u_c,   u_ip1, uf_m, dtdx);
        float Fjp = face_flux(u_jm1, u_c,   u_jp1, u_jp2, vf_p, dtdx);
        float Fjm = face_flux(u_jm2, u_jm1, u_c,   u_jp1, vf_m, dtdx);
        float tend = -((Fip - Fim) + (Fjp - Fjm)) * INVDX;
        float lap  = (u_im1 + u_ip1 + u_jm1 + u_jp1 - 4.0f*u_c) * INVDX2;
        un[idx] = u_c + dt*(tend + VISCF*lap);
    }
    {
        float Fip = face_flux(v_im1, v_c,   v_ip1, v_ip2, uf_p, dtdx);
        float Fim = face_flux(v_im2, v_im1, v_c,   v_ip1, uf_m, dtdx);
        float Fjp = face_flux(v_jm1, v_c,   v_jp1, v_jp2, vf_p, dtdx);
        float Fjm = face_flux(v_jm2, v_jm1, v_c,   v_jp1, vf_m, dtdx);
        float tend = -((Fip - Fim) + (Fjp - Fjm)) * INVDX;
        float lap  = (v_im1 + v_ip1 + v_jm1 + v_jp1 - 4.0f*v_c) * INVDX2;
        vn[idx] = v_c + dt*(tend + VISCF*lap);
    }
    {
        float Fip = face_flux(d_im1, d_c,   d_ip1, d_ip2, uf_p, dtdx);
        float Fim = face_flux(d_im2, d_im1, d_c,   d_ip1, uf_m, dtdx);
        float Fjp = face_flux(d_jm1, d_c,   d_jp1, d_jp2, vf_p, dtdx);
        float Fjm = face_flux(d_jm2, d_jm1, d_c,   d_jp1, vf_m, dtdx);
        float tend = -((Fip - Fim) + (Fjp - Fjm)) * INVDX;
        dout[idx] = d_c + dt*tend;
    }
}

// ---------------- K2: divergence + paired real row FFT (r2c) ----------------
// 64 threads/block = 4 FFTs (warp-local, 2 per warp). One FFT per row pair.
__global__ void k_divfft(int upar){
    __shared__ float2 stw[256];
    __shared__ float2 tb[4*272];
    const float* __restrict__ u1 = upar ? g_uB : g_uA;
    const float* __restrict__ v1 = upar ? g_vB : g_vA;
    int tid = threadIdx.x;                // 64
    #pragma unroll
    for (int m = 0; m < 4; m++) stw[tid + 64*m] = g_twf[tid + 64*m];
    __syncthreads();

    int f = tid >> 4, t = tid & 15;
    int fftid = blockIdx.x*4 + f;         // 0..1023
    int b = fftid >> 7, mp = fftid & 127;
    int r0 = 2*mp, r1 = r0 + 1;
    int base = b << 16;
    int row0 = base + (r0<<8), rowm = base + (((r0-1)&255)<<8), row1 = base + (r1<<8);

    float2 x[16];
    #pragma unroll
    for (int n1 = 0; n1 < 16; n1++){
        int j = 16*n1 + t, jm = (j-1)&255;
        float u0c = __ldg(&u1[row0+j]);
        float du0 = u0c - __ldg(&u1[rowm+j]);
        float dv0 = __ldg(&v1[row0+j]) - __ldg(&v1[row0+jm]);
        float du1 = __ldg(&u1[row1+j]) - u0c;
        float dv1 = __ldg(&v1[row1+j]) - __ldg(&v1[row1+jm]);
        x[n1] = make_float2((du0+dv0)*INVDX, (du1+dv1)*INVDX);
    }
    float2* tbf = &tb[f*272];
    fftcore<-1,false>(x, t, tbf, stw);
    // stash full spectrum Z[t+16*k2] at [k2*17+t] for the hermitian untangle
    __syncwarp();
    #pragma unroll
    for (int k2 = 0; k2 < 16; k2++) tbf[k2*17 + t] = x[k2];
    __syncwarp();
    int gb0 = (b*NG + r0)*K2P, gb1 = (b*NG + r1)*K2P;
    #pragma unroll
    for (int m = 0; m < 9; m++){
        int k = t + 16*m;
        if (k <= 128){
            float2 Z  = tbf[m*17 + t];
            int kk = (256-k)&255;
            float2 Zn = tbf[(kk>>4)*17 + (kk&15)];
            g_G[gb0+k] = make_float2(0.5f*(Z.x+Zn.x), 0.5f*(Z.y-Zn.y));
            g_G[gb1+k] = make_float2(0.5f*(Z.y+Zn.y), 0.5f*(Zn.x-Z.x));
        }
    }
}

// ---------------- K3: column FFT * inv_lam * inverse column FFT ----------------
// 64 threads/block = 4 FFTs on 4 ADJACENT k2 (c = tid&3 for coalescing); block-sync.
__global__ void k_colsolve(){
    __shared__ float2 stw[256];
    __shared__ float2 tb[4*272];
    int tid = threadIdx.x;                // 64
    #pragma unroll
    for (int m = 0; m < 4; m++) stw[tid + 64*m] = g_twf[tid + 64*m];
    __syncthreads();

    int c = tid & 3, t = tid >> 2;        // t = 0..15
    int quad = blockIdx.x % 33, b = blockIdx.x / 33;
    int k2 = quad*4 + c;                  // 0..131 (129..131 pad: zeros in, zeros out)
    int gb = b*NG*K2P + k2;

    float2 x[16];
    #pragma unroll
    for (int n1 = 0; n1 < 16; n1++)
        x[n1] = g_G[gb + (16*n1 + t)*K2P];

    float2* tbf = &tb[c*272];
    fftcore<-1,true>(x, t, tbf, stw);

    float l2v = __ldg(&g_lam1[k2 & 255]);
    #pragma unroll
    for (int r = 0; r < 16; r++){
        int k1 = t + 16*r;
        float sc = __fdividef(ONE65536, __ldg(&g_lam1[k1]) + l2v);
        if ((k1 | k2) == 0) sc = 0.0f;
        x[r].x *= sc; x[r].y *= sc;
    }
    __syncthreads();       // protect tb reuse
    fftcore<1,true>(x, t, tbf, stw);

    #pragma unroll
    for (int r = 0; r < 16; r++)
        g_G[gb + (t + 16*r)*K2P] = x[r];
}

// ---------------- K4: paired inverse row FFT (c2r) -> q ----------------
__global__ void k_rowifft(){
    __shared__ float2 stw[256];
    __shared__ float2 tb[4*272];
    int tid = threadIdx.x;                // 64
    #pragma unroll
    for (int m = 0; m < 4; m++) stw[tid + 64*m] = g_twf[tid + 64*m];
    __syncthreads();

    int f = tid >> 4, t = tid & 15;
    int fftid = blockIdx.x*4 + f;
    int b = fftid >> 7, mp = fftid & 127;
    int r0 = 2*mp, r1 = r0 + 1;
    int gb0 = (b*NG + r0)*K2P, gb1 = (b*NG + r1)*K2P;

    float2 x[16];
    #pragma unroll
    for (int n1 = 0; n1 < 16; n1++){
        int k = 16*n1 + t;
        float2 W;
        if (k <= 128){
            float2 B0 = g_G[gb0+k], B1 = g_G[gb1+k];
            W = make_float2(B0.x - B1.y, B0.y + B1.x);
        } else {
            int kp = 256 - k;
            float2 B0 = g_G[gb0+kp], B1 = g_G[gb1+kp];
            W = make_float2(B0.x + B1.y, B1.x - B0.y);
        }
        x[n1] = W;
    }
    float2* tbf = &tb[f*272];
    fftcore<1,false>(x, t, tbf, stw);
    int q0 = (b<<16) + (r0<<8), q1 = (b<<16) + (r1<<8);
    #pragma unroll
    for (int m = 0; m < 16; m++){
        int j = t + 16*m;
        g_q[q0 + j] = x[m].x;
        g_q[q1 + j] = x[m].y;
    }
}

// ---------------- K5 (per outer step): corrected state -> output slice ----------------
__global__ void k_out(float* __restrict__ out, int tstep, int uparNew, int dparNew){
    int idx  = blockIdx.x*256 + threadIdx.x;
    int j    = idx & 255;
    int i    = (idx >> 8) & 255;
    int base = idx & ~0xFFFF;
    int i0   = i << 8;
    int ip1  = ((i + 1) & 255) << 8;
    int jp1  = (j + 1) & 255;

    const float* __restrict__ u1 = uparNew ? g_uB : g_uA;
    const float* __restrict__ v1 = uparNew ? g_vB : g_vA;
    const float* __restrict__ dn = dparNew ? g_d1 : g_d0;

    float qc  = g_q[idx];
    float qip = g_q[base + ip1 + j];
    float qjp = g_q[base + i0 + jp1];

    float un = u1[idx] - (qip - qc) * INVDX;
    float vn = v1[idx] - (qjp - qc) * INVDX;
    float dd = dn[idx];

    int b  = idx >> 16;
    int ij = idx & 0xFFFF;
    size_t o = ((size_t)b * TSTEPS + (size_t)tstep) * (size_t)(NG*NG*3) + (size_t)ij * 3;
    out[o + 0] = un;
    out[o + 1] = vn;
    out[o + 2] = dd;
}

// ---------------- launch ----------------
extern "C" void kernel_launch(void* const* d_in, const int* in_sizes, int n_in,
                              void* d_out, int out_size){
    const float* y0  = (const float*)d_in[0];
    const float* dtp = (const float*)d_in[1];
    float* out = (float*)d_out;

    k_tables<<<1, 256>>>();
    k_init<<<NPTS/256, 256>>>(y0);

    int upar = 0;   // current u1 in A; q starts at 0 (so corrected == u1)
    int dpar = 0;   // current density in d0
    for (int t = 0; t < TSTEPS; t++){
        for (int k = 0; k < INNERS; k++){
            k_stepF<<<NPTS/256, 256>>>(dtp, dpar, upar);
            int uparNew = upar ^ 1;
            int dparNew = dpar ^ 1;
            k_divfft  <<<256, 64>>>(uparNew);
            k_colsolve<<<264, 64>>>();
            k_rowifft <<<256, 64>>>();
            if (k == INNERS-1)
                k_out<<<NPTS/256, 256>>>(out, t, uparNew, dparNew);
            upar = uparNew;
            dpar = dparNew;
        }
    }
}